// round 1
// baseline (speedup 1.0000x reference)
#include <cuda_runtime.h>
#include <cstdint>

#define Bn 4
#define Cn 7
#define Hn 512
#define Wn 1024
#define HW (Hn*Wn)
#define NID 7
#define NBINS (1<<17)
#define BIN_SCALE 65536.0f            /* NBINS / 2.0 : errors live in [0,2] */
#define XSTEP (2.0f/2047.0f)          /* linspace(0,2,2048) step */
#define YSTEP (1.0f/1023.0f)          /* linspace(0,1,1024) step */

// ---- scratch (static device memory; no allocations) ----
__device__ unsigned g_hist[Bn*NID*NBINS*2];   // [b][id][bin][{neg,pos}] ~29.4MB
__device__ double   g_stats[Bn*NID*7];        // cnt, Sx, Sy, Ss0, Ss1, Sq0, Sq1
__device__ float    g_params[Bn*NID*4];       // c0, c1, sexp0, sexp1
__device__ double   g_seedfg[Bn*NID];
__device__ double   g_cls[Bn*4];              // focal_sum, valid_cnt, seed_bg, pad
__device__ float    g_instl[Bn*NID];

// ------------------------------------------------------------------
__global__ void zero_kernel() {
    size_t idx = (size_t)blockIdx.x * blockDim.x + threadIdx.x;
    const size_t n4 = (size_t)Bn*NID*NBINS*2/4;
    if (idx < n4) ((uint4*)g_hist)[idx] = make_uint4(0u,0u,0u,0u);
    if (idx < Bn*NID*7) g_stats[idx] = 0.0;
    if (idx < Bn*NID)   g_seedfg[idx] = 0.0;
    if (idx < Bn*4)     g_cls[idx] = 0.0;
}

// ------------------------------------------------------------------
// Phase 1: per-(b,id) stats. center uses COORDINATE maps (not emb).
__global__ __launch_bounds__(256) void phase1_kernel(
        const float* __restrict__ pred, const int* __restrict__ inst) {
    __shared__ float acc[NID*7];
    int tid = threadIdx.x;
    if (tid < NID*7) acc[tid] = 0.f;
    __syncthreads();
    int b = blockIdx.y;
    const float* s0p = pred + ((size_t)b*Cn + 2)*HW;
    const float* s1p = pred + ((size_t)b*Cn + 3)*HW;
    const int*   ip  = inst + (size_t)b*HW;
    for (int i = blockIdx.x*blockDim.x + tid; i < HW; i += blockDim.x*gridDim.x) {
        int v = ip[i];
        if (v >= 1) {
            int id = v - 1;
            float x = (float)(i & (Wn-1)) * XSTEP;
            float y = (float)(i >> 10)    * YSTEP;
            float a = s0p[i], c = s1p[i];
            float* p = acc + id*7;
            atomicAdd(p+0, 1.f);
            atomicAdd(p+1, x);
            atomicAdd(p+2, y);
            atomicAdd(p+3, a);
            atomicAdd(p+4, c);
            atomicAdd(p+5, a*a);
            atomicAdd(p+6, c*c);
        }
    }
    __syncthreads();
    if (tid < NID*7) atomicAdd(&g_stats[b*NID*7 + tid], (double)acc[tid]);
}

// ------------------------------------------------------------------
__global__ void prep_kernel() {
    int t = threadIdx.x;
    if (t >= Bn*NID) return;
    const double* s = &g_stats[t*7];
    double cnt = s[0];
    double cn = cnt > 1.0 ? cnt : 1.0;
    g_params[t*4+0] = (float)(s[1]/cn);
    g_params[t*4+1] = (float)(s[2]/cn);
    g_params[t*4+2] = (float)exp(10.0 * s[3]/cn);
    g_params[t*4+3] = (float)exp(10.0 * s[4]/cn);
}

// ------------------------------------------------------------------
__device__ __forceinline__ float fast_tanh(float x) {
    float t = __expf(-2.0f * fabsf(x));
    float r = __fdividef(1.0f - t, 1.0f + t);
    return copysignf(r, x);
}

__device__ __forceinline__ float blockSum256(float v, float* red, int tid) {
    #pragma unroll
    for (int o = 16; o > 0; o >>= 1) v += __shfl_down_sync(0xffffffffu, v, o);
    if ((tid & 31) == 0) red[tid >> 5] = v;
    __syncthreads();
    if (tid < 32) {
        v = (tid < 8) ? red[tid] : 0.f;
        #pragma unroll
        for (int o = 4; o > 0; o >>= 1) v += __shfl_down_sync(0xffffffffu, v, o);
    }
    __syncthreads();
    return v;   // valid on tid==0
}

// Phase 2: per pixel -> 7 dist evals -> error histogram; + seed_fg, focal, seed_bg.
__global__ __launch_bounds__(256) void phase2_kernel(
        const float* __restrict__ pred, const int* __restrict__ inst,
        const int* __restrict__ lab) {
    __shared__ float sfg[NID];
    __shared__ float red[8];
    int tid = threadIdx.x;
    int b = blockIdx.y;
    if (tid < NID) sfg[tid] = 0.f;
    __syncthreads();

    float4 prm[NID];
    #pragma unroll
    for (int id = 0; id < NID; id++)
        prm[id] = __ldg(((const float4*)g_params) + b*NID + id);

    const float* p0p = pred + ((size_t)b*Cn + 0)*HW;
    const float* p1p = pred + ((size_t)b*Cn + 1)*HW;
    const float* p4p = pred + ((size_t)b*Cn + 4)*HW;
    const float* p5p = pred + ((size_t)b*Cn + 5)*HW;
    const float* p6p = pred + ((size_t)b*Cn + 6)*HW;
    const int*   ip  = inst + (size_t)b*HW;
    const int*   lp  = lab  + (size_t)b*HW;
    unsigned* hb = g_hist + (size_t)b*NID*NBINS*2;

    float clsS = 0.f, vcnt = 0.f, sbg = 0.f;

    for (int i = blockIdx.x*blockDim.x + tid; i < HW; i += blockDim.x*gridDim.x) {
        int v = ip[i];
        int l = lp[i];
        float x = (float)(i & (Wn-1)) * XSTEP;
        float y = (float)(i >> 10)    * YSTEP;
        float e0 = fast_tanh(p0p[i]) + x;
        float e1 = fast_tanh(p1p[i]) + y;
        float seed = __fdividef(1.f, 1.f + __expf(-p4p[i]));

        #pragma unroll
        for (int id = 0; id < NID; id++) {
            float dx = e0 - prm[id].x;
            float dy = e1 - prm[id].y;
            float q  = dx*dx*prm[id].z + dy*dy*prm[id].w;
            float d  = __expf(-q);
            bool pos = (v == id + 1);
            float e  = pos ? fmaf(-2.f, d, 2.f) : 2.f*d;
            int bin = (int)(e * BIN_SCALE);
            bin = bin < NBINS-1 ? bin : NBINS-1;
            bin = bin > 0 ? bin : 0;
            atomicAdd(hb + (((size_t)id*NBINS + bin) << 1) + (pos ? 1 : 0), 1u);
            if (pos) { float df = seed - d; atomicAdd(&sfg[id], df*df); }
        }
        if (l < 2) {
            float xt = l ? p6p[i] : p5p[i];
            float xo = l ? p5p[i] : p6p[i];
            float u = __expf(xo - xt);
            float logpt = -log1pf(u);
            float pt = __fdividef(1.f, 1.f + u);
            float om = 1.f - pt;
            clsS += -om*om*logpt;
            vcnt += 1.f;
        }
        if (l == 0) sbg += seed*seed;
    }

    float s;
    s = blockSum256(clsS, red, tid); if (tid == 0) atomicAdd(&g_cls[b*4+0], (double)s);
    __syncthreads();
    s = blockSum256(vcnt, red, tid); if (tid == 0) atomicAdd(&g_cls[b*4+1], (double)s);
    __syncthreads();
    s = blockSum256(sbg,  red, tid); if (tid == 0) atomicAdd(&g_cls[b*4+2], (double)s);
    __syncthreads();
    if (tid < NID) atomicAdd(&g_seedfg[b*NID + tid], (double)sfg[tid]);
}

// ------------------------------------------------------------------
// Scan: one block per (b,id). Descending-error walk over histogram.
__global__ __launch_bounds__(512) void scan_kernel() {
    __shared__ unsigned sp[512], sn[512];
    __shared__ float red[16];
    int t = threadIdx.x;
    int bi = blockIdx.x;                       // 0..27
    const uint2* h = (const uint2*)g_hist + (size_t)bi*NBINS;
    const int BPT = NBINS/512;                 // 256 bins per thread

    unsigned lp = 0, ln = 0;
    int r0 = t * BPT;
    for (int k = 0; k < BPT; k++) {
        uint2 c = h[NBINS-1 - (r0 + k)];
        ln += c.x; lp += c.y;                  // .x = neg, .y = pos
    }
    sp[t] = lp; sn[t] = ln;
    __syncthreads();
    for (int o = 1; o < 512; o <<= 1) {        // Hillis-Steele inclusive scan
        unsigned a = 0, bsum = 0;
        if (t >= o) { a = sp[t-o]; bsum = sn[t-o]; }
        __syncthreads();
        sp[t] += a; sn[t] += bsum;
        __syncthreads();
    }
    unsigned Ptot = sp[511];

    float acc = 0.f;
    if (Ptot > 0) {
        float P = (float)Ptot;
        float p = (float)(sp[t] - lp);         // exclusive prefix (descending order)
        float n = (float)(sn[t] - ln);
        const float escale = 2.0f / (float)NBINS;
        for (int k = 0; k < BPT; k++) {
            int bin = NBINS-1 - (r0 + k);
            uint2 c = h[bin];
            if (c.x | c.y) {
                float cp = (float)c.y, cn = (float)c.x;
                // djac = [cp*(P+n_b) + cn*(P-p_b)] / [(P+n_b)*(P+n_a)]  (no cancellation)
                float num = cp*(P + n) + cn*(P - p);
                float den = (P + n) * (P + n + cn);
                float ec  = ((float)bin + 0.5f) * escale;
                acc += ec * __fdividef(num, den);
                p += cp; n += cn;
            }
        }
    }
    // block reduce (512 threads -> 16 warps)
    #pragma unroll
    for (int o = 16; o > 0; o >>= 1) acc += __shfl_down_sync(0xffffffffu, acc, o);
    if ((t & 31) == 0) red[t >> 5] = acc;
    __syncthreads();
    if (t < 32) {
        float v = (t < 16) ? red[t] : 0.f;
        #pragma unroll
        for (int o = 8; o > 0; o >>= 1) v += __shfl_down_sync(0xffffffffu, v, o);
        if (t == 0) g_instl[bi] = v;
    }
}

// ------------------------------------------------------------------
__global__ void final_kernel(float* out) {
    double totalL = 0.0, totalC = 0.0;
    for (int b = 0; b < Bn; b++) {
        double obj = 0.0, instS = 0.0, varS = 0.0, sfgS = 0.0;
        for (int id = 0; id < NID; id++) {
            const double* s = &g_stats[(b*NID + id)*7];
            double cnt = s[0];
            if (cnt > 0.0) {
                double m0 = s[3]/cnt, m1 = s[4]/cnt;
                double var = ((s[5] - cnt*m0*m0) + (s[6] - cnt*m1*m1)) / (2.0*cnt);
                obj += 1.0;
                varS += var;
                instS += (double)g_instl[b*NID + id];
                sfgS  += 200.0 * g_seedfg[b*NID + id];
            }
        }
        if (obj < 1.0) obj = 1.0;
        double seed_loss = (g_cls[b*4+2] + sfgS) / (double)HW;
        double loss_b = instS/obj + 10.0*(varS/obj) + seed_loss;
        double vc = g_cls[b*4+1]; if (vc < 1.0) vc = 1.0;
        totalL += loss_b;
        totalC += g_cls[b*4+0] / vc;
    }
    out[0] = (float)(totalL/(double)Bn + totalC/(double)Bn);
}

// ------------------------------------------------------------------
extern "C" void kernel_launch(void* const* d_in, const int* in_sizes, int n_in,
                              void* d_out, int out_size) {
    const float* pred = (const float*)d_in[0];
    const int*   inst = (const int*)d_in[1];
    const int*   lab  = (const int*)d_in[2];
    float* out = (float*)d_out;

    const int n4 = Bn*NID*NBINS*2/4;
    zero_kernel<<<(n4 + 255)/256, 256>>>();
    phase1_kernel<<<dim3(512, Bn), 256>>>(pred, inst);
    prep_kernel<<<1, 32>>>();
    phase2_kernel<<<dim3(512, Bn), 256>>>(pred, inst, lab);
    scan_kernel<<<Bn*NID, 512>>>();
    final_kernel<<<1, 1>>>(out);
}

// round 2
// speedup vs baseline: 1.9730x; 1.9730x over previous
#include <cuda_runtime.h>
#include <cstdint>

#define Bn 4
#define Cn 7
#define Hn 512
#define Wn 1024
#define HW (Hn*Wn)
#define NID 7
#define NBINS 16384
#define BIN_SCALE 8192.0f             /* NBINS / 2.0 : errors live in [0,2] */
#define Q_SKIP 9.7041f                /* ln(NBINS) : exp(-q) below => bin 0 */
#define XSTEP (2.0f/2047.0f)
#define YSTEP (1.0f/1023.0f)

// ---- scratch (static device memory; no allocations) ----
__device__ unsigned g_hist[Bn*NID*NBINS*2];   // [b][id][bin][{neg,pos}] 3.67MB
__device__ double   g_stats[Bn*NID*7];        // cnt, Sx, Sy, Ss0, Ss1, Sq0, Sq1
__device__ float    g_params[Bn*NID*4];       // c0, c1, sexp0, sexp1
__device__ double   g_seedfg[Bn*NID];
__device__ double   g_cls[Bn*4];              // focal_sum, valid_cnt, seed_bg, pad
__device__ float    g_instl[Bn*NID];

// ------------------------------------------------------------------
__global__ void zero_kernel() {
    size_t idx = (size_t)blockIdx.x * blockDim.x + threadIdx.x;
    const size_t n4 = (size_t)Bn*NID*NBINS*2/4;
    if (idx < n4) ((uint4*)g_hist)[idx] = make_uint4(0u,0u,0u,0u);
    if (idx < Bn*NID*7) g_stats[idx] = 0.0;
    if (idx < Bn*NID)   g_seedfg[idx] = 0.0;
    if (idx < Bn*4)     g_cls[idx] = 0.0;
}

// ------------------------------------------------------------------
// Phase 1: per-(b,id) stats; per-warp shared banks cut ATOMS contention 8x.
__global__ __launch_bounds__(256) void phase1_kernel(
        const float* __restrict__ pred, const int* __restrict__ inst) {
    __shared__ float acc[8][NID*7];
    int tid = threadIdx.x, w = tid >> 5;
    for (int i = tid; i < 8*NID*7; i += 256) ((float*)acc)[i] = 0.f;
    __syncthreads();
    int b = blockIdx.y;
    const float* s0p = pred + ((size_t)b*Cn + 2)*HW;
    const float* s1p = pred + ((size_t)b*Cn + 3)*HW;
    const int*   ip  = inst + (size_t)b*HW;
    for (int i = blockIdx.x*blockDim.x + tid; i < HW; i += blockDim.x*gridDim.x) {
        int v = ip[i];
        if (v >= 1) {
            int id = v - 1;
            float x = (float)(i & (Wn-1)) * XSTEP;
            float y = (float)(i >> 10)    * YSTEP;
            float a = s0p[i], c = s1p[i];
            float* p = acc[w] + id*7;
            atomicAdd(p+0, 1.f);
            atomicAdd(p+1, x);
            atomicAdd(p+2, y);
            atomicAdd(p+3, a);
            atomicAdd(p+4, c);
            atomicAdd(p+5, a*a);
            atomicAdd(p+6, c*c);
        }
    }
    __syncthreads();
    for (int i = tid; i < NID*7; i += 256) {
        float s = 0.f;
        #pragma unroll
        for (int k = 0; k < 8; k++) s += acc[k][i];
        atomicAdd(&g_stats[b*NID*7 + i], (double)s);
    }
}

// ------------------------------------------------------------------
__global__ void prep_kernel() {
    int t = threadIdx.x;
    if (t >= Bn*NID) return;
    const double* s = &g_stats[t*7];
    double cnt = s[0];
    double cn = cnt > 1.0 ? cnt : 1.0;
    g_params[t*4+0] = (float)(s[1]/cn);
    g_params[t*4+1] = (float)(s[2]/cn);
    g_params[t*4+2] = (float)exp(10.0 * s[3]/cn);
    g_params[t*4+3] = (float)exp(10.0 * s[4]/cn);
}

// ------------------------------------------------------------------
__device__ __forceinline__ float fast_tanh(float x) {
    float t = __expf(-2.0f * fabsf(x));
    float r = __fdividef(1.0f - t, 1.0f + t);
    return copysignf(r, x);
}

__device__ __forceinline__ float blockSum256(float v, float* red, int tid) {
    #pragma unroll
    for (int o = 16; o > 0; o >>= 1) v += __shfl_down_sync(0xffffffffu, v, o);
    if ((tid & 31) == 0) red[tid >> 5] = v;
    __syncthreads();
    if (tid < 32) {
        v = (tid < 8) ? red[tid] : 0.f;
        #pragma unroll
        for (int o = 4; o > 0; o >>= 1) v += __shfl_down_sync(0xffffffffu, v, o);
    }
    __syncthreads();
    return v;   // valid on tid==0
}

// Phase 2: per pixel -> 7 dist evals -> error histogram; + seed_fg, focal, seed_bg.
// Neg pixels with q > ln(NBINS) provably land in bin 0: skip exp AND atomic,
// count locally in registers, flush once per block.
__global__ __launch_bounds__(256) void phase2_kernel(
        const float* __restrict__ pred, const int* __restrict__ inst,
        const int* __restrict__ lab) {
    __shared__ float sfg[NID];
    __shared__ unsigned sb0[NID];
    __shared__ float red[8];
    int tid = threadIdx.x;
    int b = blockIdx.y;
    if (tid < NID) { sfg[tid] = 0.f; sb0[tid] = 0u; }
    __syncthreads();

    float4 prm[NID];
    #pragma unroll
    for (int id = 0; id < NID; id++)
        prm[id] = __ldg(((const float4*)g_params) + b*NID + id);

    const float* p0p = pred + ((size_t)b*Cn + 0)*HW;
    const float* p1p = pred + ((size_t)b*Cn + 1)*HW;
    const float* p4p = pred + ((size_t)b*Cn + 4)*HW;
    const float* p5p = pred + ((size_t)b*Cn + 5)*HW;
    const float* p6p = pred + ((size_t)b*Cn + 6)*HW;
    const int*   ip  = inst + (size_t)b*HW;
    const int*   lp  = lab  + (size_t)b*HW;
    unsigned* hb = g_hist + (size_t)b*NID*NBINS*2;

    float clsS = 0.f, vcnt = 0.f, sbg = 0.f;
    unsigned b0[NID];
    #pragma unroll
    for (int id = 0; id < NID; id++) b0[id] = 0u;

    for (int i = blockIdx.x*blockDim.x + tid; i < HW; i += blockDim.x*gridDim.x) {
        int v = ip[i];
        int l = lp[i];
        float x = (float)(i & (Wn-1)) * XSTEP;
        float y = (float)(i >> 10)    * YSTEP;
        float e0 = fast_tanh(p0p[i]) + x;
        float e1 = fast_tanh(p1p[i]) + y;
        float seed = __fdividef(1.f, 1.f + __expf(-p4p[i]));

        #pragma unroll
        for (int id = 0; id < NID; id++) {
            float dx = e0 - prm[id].x;
            float dy = e1 - prm[id].y;
            float q  = dx*dx*prm[id].z + dy*dy*prm[id].w;
            bool pos = (v == id + 1);
            if (!pos && q > Q_SKIP) {
                b0[id]++;                         // provably bin 0, neg
            } else {
                float d  = __expf(-q);
                float e  = pos ? fmaf(-2.f, d, 2.f) : 2.f*d;
                int bin = (int)(e * BIN_SCALE);
                bin = bin < NBINS-1 ? bin : NBINS-1;
                bin = bin > 0 ? bin : 0;
                if (!pos && bin == 0) {
                    b0[id]++;
                } else {
                    atomicAdd(hb + (((size_t)id*NBINS + bin) << 1) + (pos ? 1 : 0), 1u);
                }
                if (pos) { float df = seed - d; atomicAdd(&sfg[id], df*df); }
            }
        }
        if (l < 2) {
            float xt = l ? p6p[i] : p5p[i];
            float xo = l ? p5p[i] : p6p[i];
            float u = __expf(xo - xt);
            float logpt = -log1pf(u);
            float pt = __fdividef(1.f, 1.f + u);
            float om = 1.f - pt;
            clsS += -om*om*logpt;
            vcnt += 1.f;
        }
        if (l == 0) sbg += seed*seed;
    }

    #pragma unroll
    for (int id = 0; id < NID; id++)
        if (b0[id]) atomicAdd(&sb0[id], b0[id]);

    float s;
    s = blockSum256(clsS, red, tid); if (tid == 0) atomicAdd(&g_cls[b*4+0], (double)s);
    __syncthreads();
    s = blockSum256(vcnt, red, tid); if (tid == 0) atomicAdd(&g_cls[b*4+1], (double)s);
    __syncthreads();
    s = blockSum256(sbg,  red, tid); if (tid == 0) atomicAdd(&g_cls[b*4+2], (double)s);
    __syncthreads();
    if (tid < NID) {
        atomicAdd(&g_seedfg[b*NID + tid], (double)sfg[tid]);
        if (sb0[tid]) atomicAdd(hb + (size_t)tid*NBINS*2, sb0[tid]);  // bin0, neg slot
    }
}

// ------------------------------------------------------------------
// Scan: one block per (b,id). Descending-error walk over histogram.
__global__ __launch_bounds__(512) void scan_kernel() {
    __shared__ unsigned sp[512], sn[512];
    __shared__ float red[16];
    int t = threadIdx.x;
    int bi = blockIdx.x;                       // 0..27
    const uint2* h = (const uint2*)g_hist + (size_t)bi*NBINS;
    const int BPT = NBINS/512;                 // 32 bins per thread

    unsigned lp = 0, ln = 0;
    int r0 = t * BPT;
    #pragma unroll 4
    for (int k = 0; k < BPT; k++) {
        uint2 c = h[NBINS-1 - (r0 + k)];
        ln += c.x; lp += c.y;                  // .x = neg, .y = pos
    }
    sp[t] = lp; sn[t] = ln;
    __syncthreads();
    for (int o = 1; o < 512; o <<= 1) {        // Hillis-Steele inclusive scan
        unsigned a = 0, bsum = 0;
        if (t >= o) { a = sp[t-o]; bsum = sn[t-o]; }
        __syncthreads();
        sp[t] += a; sn[t] += bsum;
        __syncthreads();
    }
    unsigned Ptot = sp[511];

    float acc = 0.f;
    if (Ptot > 0) {
        float P = (float)Ptot;
        float p = (float)(sp[t] - lp);         // exclusive prefix (descending order)
        float n = (float)(sn[t] - ln);
        const float escale = 2.0f / (float)NBINS;
        for (int k = 0; k < BPT; k++) {
            int bin = NBINS-1 - (r0 + k);
            uint2 c = h[bin];
            if (c.x | c.y) {
                float cp = (float)c.y, cn = (float)c.x;
                // djac = [cp*(P+n_b) + cn*(P-p_b)] / [(P+n_b)*(P+n_a)]
                float num = cp*(P + n) + cn*(P - p);
                float den = (P + n) * (P + n + cn);
                float ec  = ((float)bin + 0.5f) * escale;
                acc += ec * __fdividef(num, den);
                p += cp; n += cn;
            }
        }
    }
    #pragma unroll
    for (int o = 16; o > 0; o >>= 1) acc += __shfl_down_sync(0xffffffffu, acc, o);
    if ((t & 31) == 0) red[t >> 5] = acc;
    __syncthreads();
    if (t < 32) {
        float v = (t < 16) ? red[t] : 0.f;
        #pragma unroll
        for (int o = 8; o > 0; o >>= 1) v += __shfl_down_sync(0xffffffffu, v, o);
        if (t == 0) g_instl[bi] = v;
    }
}

// ------------------------------------------------------------------
// Final: 32 threads so the ~270 global loads overlap (MLP across lanes).
__global__ void final_kernel(float* out) {
    __shared__ double shP[Bn*NID], shV[Bn*NID], shI[Bn*NID], shS[Bn*NID];
    int t = threadIdx.x;
    if (t < Bn*NID) {
        const double* s = &g_stats[t*7];
        double cnt = s[0];
        double pres = 0.0, var = 0.0, inl = 0.0, sf = 0.0;
        if (cnt > 0.0) {
            double m0 = s[3]/cnt, m1 = s[4]/cnt;
            pres = 1.0;
            var = ((s[5] - cnt*m0*m0) + (s[6] - cnt*m1*m1)) / (2.0*cnt);
            inl = (double)g_instl[t];
            sf  = 200.0 * g_seedfg[t];
        }
        shP[t] = pres; shV[t] = var; shI[t] = inl; shS[t] = sf;
    }
    __syncthreads();
    if (t == 0) {
        double totalL = 0.0, totalC = 0.0;
        for (int b = 0; b < Bn; b++) {
            double obj = 0.0, iS = 0.0, vS = 0.0, sS = 0.0;
            for (int id = 0; id < NID; id++) {
                int k = b*NID + id;
                obj += shP[k]; iS += shI[k]; vS += shV[k]; sS += shS[k];
            }
            if (obj < 1.0) obj = 1.0;
            double seed_loss = (g_cls[b*4+2] + sS) / (double)HW;
            totalL += iS/obj + 10.0*(vS/obj) + seed_loss;
            double vc = g_cls[b*4+1]; if (vc < 1.0) vc = 1.0;
            totalC += g_cls[b*4+0] / vc;
        }
        out[0] = (float)((totalL + totalC) / (double)Bn);
    }
}

// ------------------------------------------------------------------
extern "C" void kernel_launch(void* const* d_in, const int* in_sizes, int n_in,
                              void* d_out, int out_size) {
    const float* pred = (const float*)d_in[0];
    const int*   inst = (const int*)d_in[1];
    const int*   lab  = (const int*)d_in[2];
    float* out = (float*)d_out;

    const int n4 = Bn*NID*NBINS*2/4;
    zero_kernel<<<(n4 + 255)/256, 256>>>();
    phase1_kernel<<<dim3(512, Bn), 256>>>(pred, inst);
    prep_kernel<<<1, 32>>>();
    phase2_kernel<<<dim3(512, Bn), 256>>>(pred, inst, lab);
    scan_kernel<<<Bn*NID, 512>>>();
    final_kernel<<<1, 32>>>(out);
}

// round 3
// speedup vs baseline: 2.3430x; 1.1875x over previous
#include <cuda_runtime.h>
#include <cstdint>

#define Bn 4
#define Cn 7
#define Hn 512
#define Wn 1024
#define HW (Hn*Wn)
#define NID 7
#define NBINS 16384
#define BIN_SCALE 8192.0f             /* NBINS / 2.0 : errors live in [0,2] */
#define XSTEP (2.0f/2047.0f)
#define YSTEP (1.0f/1023.0f)

// ---- scratch (static device memory; no allocations) ----
__device__ unsigned g_hist[Bn*NID*NBINS*2];   // [b][id][bin][{neg,pos}] 3.67MB
__device__ double   g_stats[Bn*NID*7];        // cnt, Sx, Sy, Ss0, Ss1, Sq0, Sq1
__device__ float    g_params[Bn*NID*4];       // c0, c1, sexp0, sexp1
__device__ double   g_seedfg[Bn*NID];
__device__ double   g_cls[Bn*4];              // focal_sum, valid_cnt, seed_bg, pad
__device__ float    g_instl[Bn*NID];

// ------------------------------------------------------------------
__global__ void zero_kernel() {
    size_t idx = (size_t)blockIdx.x * blockDim.x + threadIdx.x;
    const size_t n4 = (size_t)Bn*NID*NBINS*2/4;
    if (idx < n4) ((uint4*)g_hist)[idx] = make_uint4(0u,0u,0u,0u);
    if (idx < Bn*NID*7) g_stats[idx] = 0.0;
    if (idx < Bn*NID)   g_seedfg[idx] = 0.0;
    if (idx < Bn*4)     g_cls[idx] = 0.0;
}

// ------------------------------------------------------------------
// Phase 1: per-(b,id) stats fully in registers (no atomics in the hot loop).
// 7 ids x {cnt, x, y, s0, s1, s0^2, s1^2} = 49 accumulators per thread.
__global__ __launch_bounds__(256) void phase1_kernel(
        const float* __restrict__ pred, const int* __restrict__ inst) {
    __shared__ float sh[NID*7];
    int tid = threadIdx.x;
    int lane = tid & 31;
    if (tid < NID*7) sh[tid] = 0.f;
    __syncthreads();

    float acc[NID][7];
    #pragma unroll
    for (int id = 0; id < NID; id++)
        #pragma unroll
        for (int k = 0; k < 7; k++) acc[id][k] = 0.f;

    int b = blockIdx.y;
    const float* s0p = pred + ((size_t)b*Cn + 2)*HW;
    const float* s1p = pred + ((size_t)b*Cn + 3)*HW;
    const int*   ip  = inst + (size_t)b*HW;

    for (int i = blockIdx.x*blockDim.x + tid; i < HW; i += blockDim.x*gridDim.x) {
        int v = ip[i];
        if (v >= 1) {
            float x = (float)(i & (Wn-1)) * XSTEP;
            float y = (float)(i >> 10)    * YSTEP;
            float a = s0p[i], c = s1p[i];
            float a2 = a*a, c2 = c*c;
            #pragma unroll
            for (int id = 0; id < NID; id++) {
                float m = (v == id+1) ? 1.f : 0.f;
                acc[id][0] += m;
                acc[id][1] = fmaf(m, x,  acc[id][1]);
                acc[id][2] = fmaf(m, y,  acc[id][2]);
                acc[id][3] = fmaf(m, a,  acc[id][3]);
                acc[id][4] = fmaf(m, c,  acc[id][4]);
                acc[id][5] = fmaf(m, a2, acc[id][5]);
                acc[id][6] = fmaf(m, c2, acc[id][6]);
            }
        }
    }

    // warp reduce each of 49 values, lane0 -> shared atomics
    float* af = (float*)acc;
    #pragma unroll
    for (int k = 0; k < NID*7; k++) {
        float v = af[k];
        #pragma unroll
        for (int o = 16; o > 0; o >>= 1) v += __shfl_down_sync(0xffffffffu, v, o);
        if (lane == 0) atomicAdd(&sh[k], v);
    }
    __syncthreads();
    if (tid < NID*7) atomicAdd(&g_stats[b*NID*7 + tid], (double)sh[tid]);
}

// ------------------------------------------------------------------
__global__ void prep_kernel() {
    int t = threadIdx.x;
    if (t >= Bn*NID) return;
    const double* s = &g_stats[t*7];
    double cnt = s[0];
    double cn = cnt > 1.0 ? cnt : 1.0;
    g_params[t*4+0] = (float)(s[1]/cn);
    g_params[t*4+1] = (float)(s[2]/cn);
    g_params[t*4+2] = (float)exp(10.0 * s[3]/cn);
    g_params[t*4+3] = (float)exp(10.0 * s[4]/cn);
}

// ------------------------------------------------------------------
__device__ __forceinline__ float fast_tanh(float x) {
    float t = __expf(-2.0f * fabsf(x));
    float r = __fdividef(1.0f - t, 1.0f + t);
    return copysignf(r, x);
}

// Phase 2: per pixel -> 7 dist evals -> error histogram via global REDG;
// seed_fg / focal / seed_bg accumulated in registers (no shared atomics).
__global__ __launch_bounds__(256) void phase2_kernel(
        const float* __restrict__ pred, const int* __restrict__ inst,
        const int* __restrict__ lab) {
    __shared__ float sh[NID + 3];
    int tid = threadIdx.x;
    int lane = tid & 31;
    int b = blockIdx.y;
    if (tid < NID + 3) sh[tid] = 0.f;
    __syncthreads();

    float4 prm[NID];
    #pragma unroll
    for (int id = 0; id < NID; id++)
        prm[id] = __ldg(((const float4*)g_params) + b*NID + id);

    const float* p0p = pred + ((size_t)b*Cn + 0)*HW;
    const float* p1p = pred + ((size_t)b*Cn + 1)*HW;
    const float* p4p = pred + ((size_t)b*Cn + 4)*HW;
    const float* p5p = pred + ((size_t)b*Cn + 5)*HW;
    const float* p6p = pred + ((size_t)b*Cn + 6)*HW;
    const int*   ip  = inst + (size_t)b*HW;
    const int*   lp  = lab  + (size_t)b*HW;
    unsigned* hb = g_hist + (size_t)b*NID*NBINS*2;

    float sfg[NID];
    #pragma unroll
    for (int id = 0; id < NID; id++) sfg[id] = 0.f;
    float clsS = 0.f, vcnt = 0.f, sbg = 0.f;

    for (int i = blockIdx.x*blockDim.x + tid; i < HW; i += blockDim.x*gridDim.x) {
        int v = ip[i];
        int l = lp[i];
        float x = (float)(i & (Wn-1)) * XSTEP;
        float y = (float)(i >> 10)    * YSTEP;
        float e0 = fast_tanh(p0p[i]) + x;
        float e1 = fast_tanh(p1p[i]) + y;
        float seed = __fdividef(1.f, 1.f + __expf(-p4p[i]));

        #pragma unroll
        for (int id = 0; id < NID; id++) {
            float dx = e0 - prm[id].x;
            float dy = e1 - prm[id].y;
            float q  = fmaf(dx*dx, prm[id].z, dy*dy*prm[id].w);
            float d  = __expf(-q);
            bool pos = (v == id + 1);
            float e  = pos ? fmaf(-2.f, d, 2.f) : 2.f*d;
            int bin = (int)(e * BIN_SCALE);
            bin = bin < NBINS-1 ? bin : NBINS-1;
            bin = bin > 0 ? bin : 0;
            atomicAdd(hb + (((size_t)id*NBINS + bin) << 1) + (pos ? 1 : 0), 1u);
            if (pos) { float df = seed - d; sfg[id] = fmaf(df, df, sfg[id]); }
        }
        if (l < 2) {
            float xt = l ? p6p[i] : p5p[i];
            float xo = l ? p5p[i] : p6p[i];
            float u = __expf(xo - xt);
            float logpt = -log1pf(u);
            float pt = __fdividef(1.f, 1.f + u);
            float om = 1.f - pt;
            clsS += -om*om*logpt;
            vcnt += 1.f;
        }
        if (l == 0) sbg += seed*seed;
    }

    // warp reduce 10 values, lane0 -> shared, then one flush per block
    float vals[NID + 3];
    #pragma unroll
    for (int id = 0; id < NID; id++) vals[id] = sfg[id];
    vals[NID+0] = clsS; vals[NID+1] = vcnt; vals[NID+2] = sbg;
    #pragma unroll
    for (int k = 0; k < NID + 3; k++) {
        float v = vals[k];
        #pragma unroll
        for (int o = 16; o > 0; o >>= 1) v += __shfl_down_sync(0xffffffffu, v, o);
        if (lane == 0) atomicAdd(&sh[k], v);
    }
    __syncthreads();
    if (tid < NID) atomicAdd(&g_seedfg[b*NID + tid], (double)sh[tid]);
    else if (tid < NID + 3) atomicAdd(&g_cls[b*4 + (tid - NID)], (double)sh[tid]);
}

// ------------------------------------------------------------------
// Scan: one block per (b,id). Descending-error walk over histogram.
__global__ __launch_bounds__(512) void scan_kernel() {
    __shared__ unsigned sp[512], sn[512];
    __shared__ float red[16];
    int t = threadIdx.x;
    int bi = blockIdx.x;                       // 0..27
    const uint2* h = (const uint2*)g_hist + (size_t)bi*NBINS;
    const int BPT = NBINS/512;                 // 32 bins per thread

    unsigned lp = 0, ln = 0;
    int r0 = t * BPT;
    #pragma unroll 4
    for (int k = 0; k < BPT; k++) {
        uint2 c = h[NBINS-1 - (r0 + k)];
        ln += c.x; lp += c.y;                  // .x = neg, .y = pos
    }
    sp[t] = lp; sn[t] = ln;
    __syncthreads();
    for (int o = 1; o < 512; o <<= 1) {        // Hillis-Steele inclusive scan
        unsigned a = 0, bsum = 0;
        if (t >= o) { a = sp[t-o]; bsum = sn[t-o]; }
        __syncthreads();
        sp[t] += a; sn[t] += bsum;
        __syncthreads();
    }
    unsigned Ptot = sp[511];

    float acc = 0.f;
    if (Ptot > 0) {
        float P = (float)Ptot;
        float p = (float)(sp[t] - lp);         // exclusive prefix (descending)
        float n = (float)(sn[t] - ln);
        const float escale = 2.0f / (float)NBINS;
        for (int k = 0; k < BPT; k++) {
            int bin = NBINS-1 - (r0 + k);
            uint2 c = h[bin];
            if (c.x | c.y) {
                float cp = (float)c.y, cn = (float)c.x;
                float num = cp*(P + n) + cn*(P - p);
                float den = (P + n) * (P + n + cn);
                float ec  = ((float)bin + 0.5f) * escale;
                acc += ec * __fdividef(num, den);
                p += cp; n += cn;
            }
        }
    }
    #pragma unroll
    for (int o = 16; o > 0; o >>= 1) acc += __shfl_down_sync(0xffffffffu, acc, o);
    if ((t & 31) == 0) red[t >> 5] = acc;
    __syncthreads();
    if (t < 32) {
        float v = (t < 16) ? red[t] : 0.f;
        #pragma unroll
        for (int o = 8; o > 0; o >>= 1) v += __shfl_down_sync(0xffffffffu, v, o);
        if (t == 0) g_instl[bi] = v;
    }
}

// ------------------------------------------------------------------
__global__ void final_kernel(float* out) {
    __shared__ double shP[Bn*NID], shV[Bn*NID], shI[Bn*NID], shS[Bn*NID];
    int t = threadIdx.x;
    if (t < Bn*NID) {
        const double* s = &g_stats[t*7];
        double cnt = s[0];
        double pres = 0.0, var = 0.0, inl = 0.0, sf = 0.0;
        if (cnt > 0.0) {
            double m0 = s[3]/cnt, m1 = s[4]/cnt;
            pres = 1.0;
            var = ((s[5] - cnt*m0*m0) + (s[6] - cnt*m1*m1)) / (2.0*cnt);
            inl = (double)g_instl[t];
            sf  = 200.0 * g_seedfg[t];
        }
        shP[t] = pres; shV[t] = var; shI[t] = inl; shS[t] = sf;
    }
    __syncthreads();
    if (t == 0) {
        double totalL = 0.0, totalC = 0.0;
        for (int b = 0; b < Bn; b++) {
            double obj = 0.0, iS = 0.0, vS = 0.0, sS = 0.0;
            for (int id = 0; id < NID; id++) {
                int k = b*NID + id;
                obj += shP[k]; iS += shI[k]; vS += shV[k]; sS += shS[k];
            }
            if (obj < 1.0) obj = 1.0;
            double seed_loss = (g_cls[b*4+2] + sS) / (double)HW;
            totalL += iS/obj + 10.0*(vS/obj) + seed_loss;
            double vc = g_cls[b*4+1]; if (vc < 1.0) vc = 1.0;
            totalC += g_cls[b*4+0] / vc;
        }
        out[0] = (float)((totalL + totalC) / (double)Bn);
    }
}

// ------------------------------------------------------------------
extern "C" void kernel_launch(void* const* d_in, const int* in_sizes, int n_in,
                              void* d_out, int out_size) {
    const float* pred = (const float*)d_in[0];
    const int*   inst = (const int*)d_in[1];
    const int*   lab  = (const int*)d_in[2];
    float* out = (float*)d_out;

    const int n4 = Bn*NID*NBINS*2/4;
    zero_kernel<<<(n4 + 255)/256, 256>>>();
    phase1_kernel<<<dim3(64, Bn), 256>>>(pred, inst);
    prep_kernel<<<1, 32>>>();
    phase2_kernel<<<dim3(256, Bn), 256>>>(pred, inst, lab);
    scan_kernel<<<Bn*NID, 512>>>();
    final_kernel<<<1, 32>>>(out);
}